// round 13
// baseline (speedup 1.0000x reference)
#include <cuda_runtime.h>
#include <cuda_fp16.h>
#include <cuda_bf16.h>

// out[row[e]] += values[e] * x[col[e]],  row sorted ascending.
// E = 1.6M, N = 100k, D = 64.
//
// Edge-balanced formulation (no row_ptr):
//   - warp = 4 groups x 8 lanes; group owns CHUNK=16 consecutive edges.
//   - lane fl gathers one uint4 (16B fp16) per edge -> 8 lanes cover the
//     full 128B fp16 feature row: exactly one L2 line per edge.
//   - segment flush (row boundary) via red.global.add.v4.f32, gated by a
//     warp-uniform ballot branch so RED+SEL issue only on boundary steps.
//   - clean path for fully-interior warps (no clamps); guarded tail path.
// Prep (1 fused kernel): convert x -> fp16 table + zero-init out.

#define N_NODES 100000
#define D_FEAT 64
#define CHUNK 16

__device__ __align__(256) __half g_x_half[(size_t)N_NODES * D_FEAT];

__global__ void __launch_bounds__(256) fused_prep_kernel(
    const float* __restrict__ x, int n4,   // convert job: n4 = floats/4
    float* __restrict__ out, int n_out4,   // zero job: out_size/4
    int conv_blocks)
{
    if ((int)blockIdx.x < conv_blocks) {
        int i = blockIdx.x * blockDim.x + threadIdx.x;
        if (i >= n4) return;
        float4 f = __ldg(&((const float4*)x)[i]);
        __half2 h0 = __floats2half2_rn(f.x, f.y);
        __half2 h1 = __floats2half2_rn(f.z, f.w);
        uint2 packed;
        packed.x = *(unsigned*)&h0;
        packed.y = *(unsigned*)&h1;
        ((uint2*)g_x_half)[i] = packed;
    } else {
        int i = (blockIdx.x - conv_blocks) * blockDim.x + threadIdx.x;
        if (i >= n_out4) return;
        ((float4*)out)[i] = make_float4(0.f, 0.f, 0.f, 0.f);
    }
}

__device__ __forceinline__ void red_add_v4(float* addr, float a, float b,
                                           float c, float d, int pred) {
    asm volatile(
        "{\n\t"
        ".reg .pred p;\n\t"
        "setp.ne.s32 p, %0, 0;\n\t"
        "@p red.global.add.v4.f32 [%1], {%2, %3, %4, %5};\n\t"
        "}" :: "r"(pred), "l"(addr), "f"(a), "f"(b), "f"(c), "f"(d) : "memory");
}

__global__ void __launch_bounds__(256) spmm_edge_chunk_kernel(
    const int* __restrict__ row,
    const int* __restrict__ col,
    const float* __restrict__ val,
    float* __restrict__ out,
    int n_edges)
{
    int gwarp = (blockIdx.x * blockDim.x + threadIdx.x) >> 5;
    int lane  = threadIdx.x & 31;
    int grp   = lane >> 3;          // which 16-edge chunk of this warp
    int fl    = lane & 7;           // owns fp16 feats [8*fl, 8*fl+8)

    int warp_base = gwarp * (4 * CHUNK);
    int base = warp_base + grp * CHUNK;

    const uint4* __restrict__ xq = (const uint4*)g_x_half;  // 8 uint4 per row

    float acc[8];
    #pragma unroll
    for (int k = 0; k < 8; ++k) acc[k] = 0.f;

    if (warp_base + 4 * CHUNK <= n_edges) {
        // ---------- clean path: whole warp strictly inside [0, n_edges) ----------
        int r_cur = __ldg(&row[base]);

        #pragma unroll
        for (int j = 0; j < CHUNK; ++j) {
            int idx = base + j;
            int   c = __ldg(&col[idx]);
            float v = __ldg(&val[idx]);

            uint4 raw = __ldg(&xq[c * (D_FEAT / 8) + fl]);   // 128B line per edge
            const __half2* hp = reinterpret_cast<const __half2*>(&raw);
            #pragma unroll
            for (int k = 0; k < 4; ++k) {
                float2 f = __half22float2(hp[k]);
                acc[2 * k]     = fmaf(v, f.x, acc[2 * k]);
                acc[2 * k + 1] = fmaf(v, f.y, acc[2 * k + 1]);
            }

            int flush, r_next;
            if (j == CHUNK - 1) {
                flush = 1; r_next = r_cur;                    // chunk end: always flush
            } else {
                r_next = __ldg(&row[idx + 1]);                // L1 broadcast hit
                flush = (r_next != r_cur);
            }

            // warp-uniform gate: skip RED+SEL entirely when no group flushes
            if (__ballot_sync(0xffffffffu, flush)) {
                float* dst = out + r_cur * D_FEAT + fl * 8;
                red_add_v4(dst,     acc[0], acc[1], acc[2], acc[3], flush);
                red_add_v4(dst + 4, acc[4], acc[5], acc[6], acc[7], flush);
                #pragma unroll
                for (int k = 0; k < 8; ++k) acc[k] = flush ? 0.f : acc[k];
            }
            r_cur = r_next;
        }
    } else {
        // ---------- guarded tail path (last warp only) ----------
        int last = n_edges - 1;
        if (last < 0) return;
        int r_cur = __ldg(&row[min(base, last)]);

        #pragma unroll
        for (int j = 0; j < CHUNK; ++j) {
            int idx  = base + j;
            int idxc = min(idx, last);
            int   c = __ldg(&col[idxc]);
            float v = (idx <= last) ? __ldg(&val[idxc]) : 0.f;
            int r_next = __ldg(&row[min(idx + 1, last)]);

            uint4 raw = __ldg(&xq[c * (D_FEAT / 8) + fl]);
            const __half2* hp = reinterpret_cast<const __half2*>(&raw);
            #pragma unroll
            for (int k = 0; k < 4; ++k) {
                float2 f = __half22float2(hp[k]);
                acc[2 * k]     = fmaf(v, f.x, acc[2 * k]);
                acc[2 * k + 1] = fmaf(v, f.y, acc[2 * k + 1]);
            }

            int flush = (j == CHUNK - 1) || (r_next != r_cur) || (idx >= last);
            if (__ballot_sync(0xffffffffu, flush)) {
                float* dst = out + r_cur * D_FEAT + fl * 8;
                red_add_v4(dst,     acc[0], acc[1], acc[2], acc[3], flush);
                red_add_v4(dst + 4, acc[4], acc[5], acc[6], acc[7], flush);
                #pragma unroll
                for (int k = 0; k < 8; ++k) acc[k] = flush ? 0.f : acc[k];
            }
            r_cur = r_next;
        }
    }
}

extern "C" void kernel_launch(void* const* d_in, const int* in_sizes, int n_in,
                              void* d_out, int out_size) {
    const int*   row = (const int*)d_in[0];
    const int*   col = (const int*)d_in[1];
    const float* val = (const float*)d_in[2];
    const float* x   = (const float*)d_in[3];
    float*       out = (float*)d_out;

    int n_edges = in_sizes[0];
    int n_x     = in_sizes[3];

    {
        int threads = 256;
        int n4 = n_x / 4;
        int n_out4 = out_size / 4;
        int conv_blocks = (n4 + threads - 1) / threads;
        int zero_blocks = (n_out4 + threads - 1) / threads;
        fused_prep_kernel<<<conv_blocks + zero_blocks, threads>>>(
            x, n4, out, n_out4, conv_blocks);
    }
    {
        int threads = 256;  // 8 warps/block; warp covers 4*CHUNK = 64 edges
        long chunks = ((long)n_edges + CHUNK - 1) / CHUNK;   // 8-lane groups
        long warps  = (chunks + 3) / 4;
        int blocks  = (int)((warps * 32 + threads - 1) / threads);
        spmm_edge_chunk_kernel<<<blocks, threads>>>(row, col, val, out, n_edges);
    }
}